// round 14
// baseline (speedup 1.0000x reference)
#include <cuda_runtime.h>
#include <cuda_fp16.h>
#include <math.h>

#define BATCH 2
#define SEQ   2048
#define NH    16
#define HD    64
#define HID   1024
#define F3    3072
#define BS    (BATCH*SEQ)
#define NBH   (BATCH*NH)        // 32

// 0.125 * log2(e)
#define C2EXP 0.1803368801111204f

// ---------------- scratch (device globals) ---------------------------------
__device__ uint4 g_qkv16[(size_t)BS * F3 / 8];           // fp16 qkv, 25.2 MB
__device__ uint4 g_x16[(size_t)BS * HID / 8];            // fp16 x
__device__ uint4 g_wq16[(size_t)HID * F3 / 8];           // fp16 w_qkv
__device__ uint4 g_wo16[(size_t)HID * HID / 8];          // fp16 w_o
__device__ uint4 g_vals16[(size_t)BS * HID / 8];         // fp16 v*colsum
__device__ float g_z[NBH * SEQ];

__device__ __forceinline__ float ex2f(float x) {
    float r; asm("ex2.approx.f32 %0, %1;" : "=f"(r) : "f"(x)); return r;
}
__device__ __forceinline__ unsigned sptr(const void* p) {
    return (unsigned)__cvta_generic_to_shared(p);
}
__device__ __forceinline__ void mma_f16(float* c, const unsigned* a, unsigned b0, unsigned b1) {
    asm volatile(
        "mma.sync.aligned.m16n8k16.row.col.f32.f16.f16.f32 "
        "{%0,%1,%2,%3}, {%4,%5,%6,%7}, {%8,%9}, {%0,%1,%2,%3};"
        : "+f"(c[0]), "+f"(c[1]), "+f"(c[2]), "+f"(c[3])
        : "r"(a[0]), "r"(a[1]), "r"(a[2]), "r"(a[3]), "r"(b0), "r"(b1));
}
__device__ __forceinline__ void ldsm4(unsigned* r, unsigned addr) {
    asm volatile("ldmatrix.sync.aligned.m8n8.x4.shared.b16 {%0,%1,%2,%3}, [%4];"
                 : "=r"(r[0]), "=r"(r[1]), "=r"(r[2]), "=r"(r[3]) : "r"(addr));
}
__device__ __forceinline__ void ldsm4t(unsigned* r, unsigned addr) {
    asm volatile("ldmatrix.sync.aligned.m8n8.x4.trans.shared.b16 {%0,%1,%2,%3}, [%4];"
                 : "=r"(r[0]), "=r"(r[1]), "=r"(r[2]), "=r"(r[3]) : "r"(addr));
}
__device__ __forceinline__ void cp16(unsigned dst, const void* src) {
    asm volatile("cp.async.cg.shared.global [%0], [%1], 16;" :: "r"(dst), "l"(src));
}
__device__ __forceinline__ unsigned pack_f16(float a, float b) {
    __half2 h = __floats2half2_rn(a, b);
    return *(unsigned*)&h;
}

// ======================= fp16 GEMM, 128x128 tile, cp.async 3-stage ==========
template <bool OUT_F16>
__global__ __launch_bounds__(256, 2) void gemm_f16(
    const uint4* __restrict__ A, const uint4* __restrict__ B, void* __restrict__ Cv,
    int K, int ldaG, int ldbG, int ldc)
{
    extern __shared__ uint4 smem[];
    uint4* sA = smem;           // [3][1024]
    uint4* sB = smem + 3072;    // [3][1024]

    const int tid = threadIdx.x, lane = tid & 31, wid = tid >> 5;
    const int wm = wid & 1, wn = wid >> 1, qr = lane >> 2, qc = lane & 3;
    const int grp = lane >> 3, lrow = lane & 7;
    const int bm0 = blockIdx.y * 128;
    const int bn0g = blockIdx.x * 16;
    const int NC = K / 64;

    const int cgA = tid & 7,  rowA0 = tid >> 3;
    const int cgB = tid & 15, rowB0 = tid >> 4;

    auto issue = [&](int c, int s) {
        const uint4* ag = A + (long)(bm0 + rowA0) * ldaG + c * 8 + cgA;
        uint4* ad = sA + s * 1024;
#pragma unroll
        for (int r = 0; r < 4; r++) {
            int row = rowA0 + r * 32;
            cp16(sptr(ad + row * 8 + (cgA ^ (row & 7))), ag + (long)r * 32 * ldaG);
        }
        const uint4* bg = B + (long)(c * 64 + rowB0) * ldbG + bn0g + cgB;
        uint4* bd = sB + s * 1024;
#pragma unroll
        for (int r = 0; r < 4; r++) {
            int row = rowB0 + r * 16;
            cp16(sptr(bd + row * 16 + (cgB ^ (row & 7))), bg + (long)r * 16 * ldbG);
        }
        asm volatile("cp.async.commit_group;");
    };

    issue(0, 0);
    if (NC > 1) issue(1, 1);
    if (NC > 2) issue(2, 2);

    float acc[4][4][4];
#pragma unroll
    for (int i = 0; i < 4; i++)
#pragma unroll
        for (int j = 0; j < 4; j++)
#pragma unroll
            for (int f = 0; f < 4; f++) acc[i][j][f] = 0.f;

    int s = 0;
#pragma unroll 1
    for (int c = 0; c < NC; c++) {
        asm volatile("cp.async.wait_group 2;");
        __syncthreads();
        const uint4* sAs = sA + s * 1024;
        const uint4* sBs = sB + s * 1024;

#pragma unroll
        for (int ks = 0; ks < 4; ks++) {
            unsigned af[4][4], bfr[2][4];
#pragma unroll
            for (int i = 0; i < 4; i++) {
                int row = wm * 64 + i * 16 + lrow + (grp & 1) * 8;
                int g = (2 * ks + (grp >> 1)) ^ (row & 7);
                ldsm4(af[i], sptr(sAs + row * 8 + g));
            }
#pragma unroll
            for (int jp = 0; jp < 2; jp++) {
                int brow = ks * 16 + (grp & 1) * 8 + lrow;
                int bg = (wn * 4 + jp * 2 + (grp >> 1)) ^ (brow & 7);
                ldsm4t(bfr[jp], sptr(sBs + brow * 16 + bg));
            }
#pragma unroll
            for (int i = 0; i < 4; i++)
#pragma unroll
                for (int jp = 0; jp < 2; jp++) {
                    mma_f16(acc[i][jp * 2 + 0], af[i], bfr[jp][0], bfr[jp][1]);
                    mma_f16(acc[i][jp * 2 + 1], af[i], bfr[jp][2], bfr[jp][3]);
                }
        }
        __syncthreads();
        if (c + 3 < NC) issue(c + 3, s);
        s = (s == 2) ? 0 : s + 1;
    }

#pragma unroll
    for (int i = 0; i < 4; i++) {
        long row = bm0 + wm * 64 + i * 16 + qr;
#pragma unroll
        for (int j = 0; j < 4; j++) {
            int col = bn0g * 8 + wn * 32 + j * 8 + 2 * qc;
            if (OUT_F16) {
                __half* C = (__half*)Cv;
                *(unsigned*)(C + row * ldc + col) = pack_f16(acc[i][j][0], acc[i][j][1]);
                *(unsigned*)(C + (row + 8) * ldc + col) = pack_f16(acc[i][j][2], acc[i][j][3]);
            } else {
                float* C = (float*)Cv;
                *(float2*)(C + row * ldc + col) = make_float2(acc[i][j][0], acc[i][j][1]);
                *(float2*)(C + (row + 8) * ldc + col) = make_float2(acc[i][j][2], acc[i][j][3]);
            }
        }
    }
}

// ======================= fused fp32 -> fp16 convert (x, w_qkv, w_o) =========
#define N_X  ((long)BS * HID / 8)        // 524288
#define N_WQ ((long)HID * F3 / 8)        // 393216
#define N_WO ((long)HID * HID / 8)       // 131072

__global__ __launch_bounds__(256) void cvt_all_kernel(
    const float4* __restrict__ x, const float4* __restrict__ wq,
    const float4* __restrict__ wo,
    uint4* __restrict__ x16, uint4* __restrict__ wq16, uint4* __restrict__ wo16)
{
    long i = (long)blockIdx.x * 256 + threadIdx.x;
    const float4* src;
    uint4* dst;
    long j;
    if (i < N_X)              { src = x;  dst = x16;  j = i; }
    else if (i < N_X + N_WQ)  { src = wq; dst = wq16; j = i - N_X; }
    else                      { src = wo; dst = wo16; j = i - N_X - N_WQ; }
    float4 v0 = src[2 * j], v1 = src[2 * j + 1];
    dst[j] = make_uint4(pack_f16(v0.x, v0.y), pack_f16(v0.z, v0.w),
                        pack_f16(v1.x, v1.y), pack_f16(v1.z, v1.w));
}

// ======================= qk pass 1: full row per CTA, plain Z store =========
// CTA: one q-block (128 rows) x ALL 2048 keys (16 streamed K tiles).
__global__ __launch_bounds__(256, 2) void qk1_kernel(
    const uint4* __restrict__ qkv16, float* __restrict__ Z)
{
    __shared__ uint4 Qs[1024];         // 16 KB resident
    __shared__ uint4 Ks[2][1024];      // 32 KB double buffer
    __shared__ float s_red[512];

    const int tid = threadIdx.x, lane = tid & 31, wid = tid >> 5;
    const int wm = wid & 1, wn = wid >> 1, qr = lane >> 2, qc = lane & 3;
    const int bz = blockIdx.y;
    const int b = bz >> 4, h = bz & 15;
    const int bm0 = blockIdx.x * 128;

    const uint4* Qg = qkv16 + (long)b * SEQ * 384 + h * 8;
    const uint4* Kg = Qg + 128;

    const int cg = tid & 7, rb = tid >> 3;

    {
        const uint4* qg = Qg + (long)(bm0 + rb) * 384 + cg;
#pragma unroll
        for (int r = 0; r < 4; r++) {
            int row = rb + r * 32;
            cp16(sptr(&Qs[row * 8 + (cg ^ (row & 7))]), qg + (long)r * 32 * 384);
        }
        const uint4* kg = Kg + (long)rb * 384 + cg;
#pragma unroll
        for (int r = 0; r < 4; r++) {
            int row = rb + r * 32;
            cp16(sptr(&Ks[0][row * 8 + (cg ^ (row & 7))]), kg + (long)r * 32 * 384);
        }
        asm volatile("cp.async.commit_group;");
    }
    {
        const uint4* kg = Kg + (long)(128 + rb) * 384 + cg;
#pragma unroll
        for (int r = 0; r < 4; r++) {
            int row = rb + r * 32;
            cp16(sptr(&Ks[1][row * 8 + (cg ^ (row & 7))]), kg + (long)r * 32 * 384);
        }
        asm volatile("cp.async.commit_group;");
    }

    const int grp = lane >> 3, lrow = lane & 7;
    const int a_roff = (grp & 1) * 8, a_kg = grp >> 1;
    const int b_roff = (grp >> 1) * 8, b_kg = grp & 1;

    float lz[4][2];
#pragma unroll
    for (int i = 0; i < 4; i++)
#pragma unroll
        for (int h2 = 0; h2 < 2; h2++) lz[i][h2] = 0.f;

#pragma unroll 1
    for (int nb = 0; nb < 16; nb++) {
        if (nb < 15) asm volatile("cp.async.wait_group 1;");
        else         asm volatile("cp.async.wait_group 0;");
        __syncthreads();

        float acc[4][4][4];
#pragma unroll
        for (int i = 0; i < 4; i++)
#pragma unroll
            for (int j = 0; j < 4; j++)
#pragma unroll
                for (int f = 0; f < 4; f++) acc[i][j][f] = 0.f;

        const uint4* Kb = Ks[nb & 1];
#pragma unroll
        for (int g = 0; g < 4; g++) {
            unsigned af[4][4], bfr[2][4];
#pragma unroll
            for (int i = 0; i < 4; i++) {
                int row = wm * 64 + i * 16 + lrow + a_roff;
                int gr = (2 * g + a_kg) ^ (row & 7);
                ldsm4(af[i], sptr(&Qs[row * 8 + gr]));
            }
#pragma unroll
            for (int jp = 0; jp < 2; jp++) {
                int row = wn * 32 + jp * 16 + lrow + b_roff;
                int gr = (2 * g + b_kg) ^ (row & 7);
                ldsm4(bfr[jp], sptr(&Kb[row * 8 + gr]));
            }
#pragma unroll
            for (int i = 0; i < 4; i++)
#pragma unroll
                for (int jp = 0; jp < 2; jp++) {
                    mma_f16(acc[i][jp * 2 + 0], af[i], bfr[jp][0], bfr[jp][1]);
                    mma_f16(acc[i][jp * 2 + 1], af[i], bfr[jp][2], bfr[jp][3]);
                }
        }
        __syncthreads();

        if (nb + 2 < 16) {
            const uint4* kg = Kg + (long)((nb + 2) * 128 + rb) * 384 + cg;
            uint4* kd = Ks[nb & 1];
#pragma unroll
            for (int r = 0; r < 4; r++) {
                int row = rb + r * 32;
                cp16(sptr(&kd[row * 8 + (cg ^ (row & 7))]), kg + (long)r * 32 * 384);
            }
            asm volatile("cp.async.commit_group;");
        }

#pragma unroll
        for (int i = 0; i < 4; i++)
#pragma unroll
            for (int h2 = 0; h2 < 2; h2++) {
#pragma unroll
                for (int j = 0; j < 4; j++) {
                    lz[i][h2] += ex2f(acc[i][j][2 * h2]     * C2EXP);
                    lz[i][h2] += ex2f(acc[i][j][2 * h2 + 1] * C2EXP);
                }
            }
    }

#pragma unroll
    for (int d = 1; d <= 2; d <<= 1)
#pragma unroll
        for (int i = 0; i < 4; i++)
#pragma unroll
            for (int h2 = 0; h2 < 2; h2++)
                lz[i][h2] += __shfl_xor_sync(0xffffffffu, lz[i][h2], d);
    __syncthreads();
    if (qc == 0)
#pragma unroll
        for (int i = 0; i < 4; i++)
#pragma unroll
            for (int h2 = 0; h2 < 2; h2++)
                s_red[wn * 128 + wm * 64 + i * 16 + h2 * 8 + qr] = lz[i][h2];
    __syncthreads();
    if (tid < 128) {
        float z = s_red[tid] + s_red[128 + tid] + s_red[256 + tid] + s_red[384 + tid];
        Z[(long)bz * SEQ + bm0 + tid] = z;          // plain store, no atomic
    }
}

// ======================= qk pass 2: K resident, full q column, fused v scale
// CTA: one key-block (128 cols) x ALL 2048 q rows (16 streamed Q tiles).
// colsum is final at CTA end -> directly writes vals16 for (rows kb0.., head h).
__global__ __launch_bounds__(256, 2) void qk2_kernel(
    const uint4* __restrict__ qkv16, const float* __restrict__ Z,
    uint4* __restrict__ vals16)
{
    extern __shared__ uint4 dsm[];
    uint4* Ks   = dsm;                    // 1024 granules (16 KB), resident
    uint4* Qs   = dsm + 1024;             // 2 x 1024 granules (32 KB)
    float* s_iz = (float*)(dsm + 3072);   // 2048 floats (8 KB) all-row 1/Z
    float* s_red = s_iz + 2048;           // 256 floats

    const int tid = threadIdx.x, lane = tid & 31, wid = tid >> 5;
    const int wm = wid & 1, wn = wid >> 1, qr = lane >> 2, qc = lane & 3;
    const int bz = blockIdx.y;
    const int b = bz >> 4, h = bz & 15;
    const int kb0 = blockIdx.x * 128;

    const uint4* Qg = qkv16 + (long)b * SEQ * 384 + h * 8;
    const uint4* Kg = Qg + 128;

    const int cg = tid & 7, rb = tid >> 3;

    // K tile (resident) + Q tile 0
    {
        const uint4* kg = Kg + (long)(kb0 + rb) * 384 + cg;
#pragma unroll
        for (int r = 0; r < 4; r++) {
            int row = rb + r * 32;
            cp16(sptr(&Ks[row * 8 + (cg ^ (row & 7))]), kg + (long)r * 32 * 384);
        }
        const uint4* qg = Qg + (long)rb * 384 + cg;
#pragma unroll
        for (int r = 0; r < 4; r++) {
            int row = rb + r * 32;
            cp16(sptr(&Qs[row * 8 + (cg ^ (row & 7))]), qg + (long)r * 32 * 384);
        }
        asm volatile("cp.async.commit_group;");
    }
    // Q tile 1
    {
        const uint4* qg = Qg + (long)(128 + rb) * 384 + cg;
#pragma unroll
        for (int r = 0; r < 4; r++) {
            int row = rb + r * 32;
            cp16(sptr(&Qs[1024 + row * 8 + (cg ^ (row & 7))]), qg + (long)r * 32 * 384);
        }
        asm volatile("cp.async.commit_group;");
    }

    // stage 1/Z for all 2048 rows (8 per thread)
#pragma unroll
    for (int r = 0; r < 8; r++) {
        int idx = tid + r * 256;
        s_iz[idx] = 1.0f / Z[(long)bz * SEQ + idx];
    }

    const int grp = lane >> 3, lrow = lane & 7;
    const int a_roff = (grp & 1) * 8, a_kg = grp >> 1;
    const int b_roff = (grp >> 1) * 8, b_kg = grp & 1;

    float cs[4][2];
#pragma unroll
    for (int j = 0; j < 4; j++) { cs[j][0] = 0.f; cs[j][1] = 0.f; }

#pragma unroll 1
    for (int qt = 0; qt < 16; qt++) {
        if (qt < 15) asm volatile("cp.async.wait_group 1;");
        else         asm volatile("cp.async.wait_group 0;");
        __syncthreads();

        float izreg[4][2];
#pragma unroll
        for (int i = 0; i < 4; i++)
#pragma unroll
            for (int h2 = 0; h2 < 2; h2++)
                izreg[i][h2] = s_iz[qt * 128 + wm * 64 + i * 16 + h2 * 8 + qr];

        float acc[4][4][4];
#pragma unroll
        for (int i = 0; i < 4; i++)
#pragma unroll
            for (int j = 0; j < 4; j++)
#pragma unroll
                for (int f = 0; f < 4; f++) acc[i][j][f] = 0.f;

        const uint4* Qb = Qs + (qt & 1) * 1024;
#pragma unroll
        for (int g = 0; g < 4; g++) {
            unsigned af[4][4], bfr[2][4];
#pragma unroll
            for (int i = 0; i < 4; i++) {
                int row = wm * 64 + i * 16 + lrow + a_roff;
                int gr = (2 * g + a_kg) ^ (row & 7);
                ldsm4(af[i], sptr(&Qb[row * 8 + gr]));
            }
#pragma unroll
            for (int jp = 0; jp < 2; jp++) {
                int row = wn * 32 + jp * 16 + lrow + b_roff;
                int gr = (2 * g + b_kg) ^ (row & 7);
                ldsm4(bfr[jp], sptr(&Ks[row * 8 + gr]));
            }
#pragma unroll
            for (int i = 0; i < 4; i++)
#pragma unroll
                for (int jp = 0; jp < 2; jp++) {
                    mma_f16(acc[i][jp * 2 + 0], af[i], bfr[jp][0], bfr[jp][1]);
                    mma_f16(acc[i][jp * 2 + 1], af[i], bfr[jp][2], bfr[jp][3]);
                }
        }
        __syncthreads();

        if (qt + 2 < 16) {
            const uint4* qg = Qg + (long)((qt + 2) * 128 + rb) * 384 + cg;
            uint4* qd = Qs + (qt & 1) * 1024;
#pragma unroll
            for (int r = 0; r < 4; r++) {
                int row = rb + r * 32;
                cp16(sptr(&qd[row * 8 + (cg ^ (row & 7))]), qg + (long)r * 32 * 384);
            }
            asm volatile("cp.async.commit_group;");
        }

#pragma unroll
        for (int i = 0; i < 4; i++)
#pragma unroll
            for (int h2 = 0; h2 < 2; h2++) {
                float iz = izreg[i][h2];
#pragma unroll
                for (int j = 0; j < 4; j++) {
                    cs[j][0] += ex2f(acc[i][j][2 * h2]     * C2EXP) * iz;
                    cs[j][1] += ex2f(acc[i][j][2 * h2 + 1] * C2EXP) * iz;
                }
            }
    }

    // reduce over qr lanes; combine warp halves -> final colsum for 128 cols
#pragma unroll
    for (int d = 4; d <= 16; d <<= 1)
#pragma unroll
        for (int j = 0; j < 4; j++) {
            cs[j][0] += __shfl_xor_sync(0xffffffffu, cs[j][0], d);
            cs[j][1] += __shfl_xor_sync(0xffffffffu, cs[j][1], d);
        }
    if (qr == 0) {
#pragma unroll
        for (int j = 0; j < 4; j++) {
            s_red[wm * 128 + wn * 32 + j * 8 + 2 * qc]     = cs[j][0];
            s_red[wm * 128 + wn * 32 + j * 8 + 2 * qc + 1] = cs[j][1];
        }
    }
    __syncthreads();
    if (tid < 128) s_red[tid] += s_red[128 + tid];
    __syncthreads();

    // fused v scale: vals[kb0+row, h*64..] = v * colsum  (rows = key positions)
#pragma unroll
    for (int r = 0; r < 4; r++) {
        int row = rb + r * 32;
        float sc = s_red[row];
        long bs = (long)b * SEQ + kb0 + row;
        uint4 v = qkv16[bs * 384 + 256 + h * 8 + cg];
        uint4 o;
        unsigned* vp = (unsigned*)&v;
        unsigned* op = (unsigned*)&o;
#pragma unroll
        for (int j = 0; j < 4; j++) {
            float2 f = __half22float2(*(__half2*)&vp[j]);
            op[j] = pack_f16(f.x * sc, f.y * sc);
        }
        vals16[bs * 128 + h * 8 + cg] = o;
    }
}

// ---------------- launcher --------------------------------------------------
#define GEMM_SMEM 98304
#define QK2_SMEM  (49152 + 8192 + 1024 + 128)   // Ks+Qs + s_iz(2048) + s_red

extern "C" void kernel_launch(void* const* d_in, const int* in_sizes, int n_in,
                              void* d_out, int out_size)
{
    const float* x     = (const float*)d_in[0];
    const float* w_qkv = (const float*)d_in[1];
    const float* w_o   = (const float*)d_in[2];
    float* out = (float*)d_out;

    float* p_z;
    uint4 *p_qkv16, *p_x16, *p_wq16, *p_wo16, *p_vals16;
    cudaGetSymbolAddress((void**)&p_z,      g_z);
    cudaGetSymbolAddress((void**)&p_qkv16,  g_qkv16);
    cudaGetSymbolAddress((void**)&p_x16,    g_x16);
    cudaGetSymbolAddress((void**)&p_wq16,   g_wq16);
    cudaGetSymbolAddress((void**)&p_wo16,   g_wo16);
    cudaGetSymbolAddress((void**)&p_vals16, g_vals16);

    cudaFuncSetAttribute(gemm_f16<true>,  cudaFuncAttributeMaxDynamicSharedMemorySize, GEMM_SMEM);
    cudaFuncSetAttribute(gemm_f16<false>, cudaFuncAttributeMaxDynamicSharedMemorySize, GEMM_SMEM);
    cudaFuncSetAttribute(qk2_kernel, cudaFuncAttributeMaxDynamicSharedMemorySize, QK2_SMEM);

    dim3 blk(256);

    // 0. convert all inputs to fp16 (one kernel)
    cvt_all_kernel<<<(int)((N_X + N_WQ + N_WO) / 256), blk>>>(
        (const float4*)x, (const float4*)w_qkv, (const float4*)w_o,
        p_x16, p_wq16, p_wo16);

    // 1. qkv(fp16) = x16 @ wq16
    gemm_f16<true><<<dim3(F3 / 128, BS / 128), blk, GEMM_SMEM>>>(
        p_x16, p_wq16, p_qkv16, HID, HID / 8, F3 / 8, F3);

    // 2. pass 1: Z[q] = sum_k exp(q.k/8)  (full row per CTA, plain store)
    qk1_kernel<<<dim3(SEQ / 128, NBH), blk>>>(p_qkv16, p_z);

    // 3. pass 2: colsum + fused v-scale -> vals16  (full column per CTA)
    qk2_kernel<<<dim3(SEQ / 128, NBH), blk, QK2_SMEM>>>(p_qkv16, p_z, p_vals16);

    // 4. out(fp32) = vals16 @ wo16
    gemm_f16<false><<<dim3(HID / 128, BS / 128), blk, GEMM_SMEM>>>(
        p_vals16, p_wo16, out, HID, HID / 8, HID / 8, HID);
}

// round 15
// speedup vs baseline: 1.0441x; 1.0441x over previous
#include <cuda_runtime.h>
#include <cuda_fp16.h>
#include <math.h>

#define BATCH 2
#define SEQ   2048
#define NH    16
#define HD    64
#define HID   1024
#define F3    3072
#define BS    (BATCH*SEQ)
#define NBH   (BATCH*NH)        // 32
#define QSTRIPS 4               // q-strips in qk2 (each 512 rows = 4 tiles)

// 0.125 * log2(e)
#define C2EXP 0.1803368801111204f

// ---------------- scratch (device globals) ---------------------------------
__device__ uint4 g_qkv16[(size_t)BS * F3 / 8];           // fp16 qkv, 25.2 MB
__device__ uint4 g_x16[(size_t)BS * HID / 8];            // fp16 x
__device__ uint4 g_wq16[(size_t)HID * F3 / 8];           // fp16 w_qkv
__device__ uint4 g_wo16[(size_t)HID * HID / 8];          // fp16 w_o
__device__ uint4 g_vals16[(size_t)BS * HID / 8];         // fp16 v*colsum
__device__ float g_z[NBH * SEQ];
__device__ float g_colsum[NBH * SEQ];

__device__ __forceinline__ float ex2f(float x) {
    float r; asm("ex2.approx.f32 %0, %1;" : "=f"(r) : "f"(x)); return r;
}
__device__ __forceinline__ unsigned sptr(const void* p) {
    return (unsigned)__cvta_generic_to_shared(p);
}
__device__ __forceinline__ void mma_f16(float* c, const unsigned* a, unsigned b0, unsigned b1) {
    asm volatile(
        "mma.sync.aligned.m16n8k16.row.col.f32.f16.f16.f32 "
        "{%0,%1,%2,%3}, {%4,%5,%6,%7}, {%8,%9}, {%0,%1,%2,%3};"
        : "+f"(c[0]), "+f"(c[1]), "+f"(c[2]), "+f"(c[3])
        : "r"(a[0]), "r"(a[1]), "r"(a[2]), "r"(a[3]), "r"(b0), "r"(b1));
}
__device__ __forceinline__ void ldsm4(unsigned* r, unsigned addr) {
    asm volatile("ldmatrix.sync.aligned.m8n8.x4.shared.b16 {%0,%1,%2,%3}, [%4];"
                 : "=r"(r[0]), "=r"(r[1]), "=r"(r[2]), "=r"(r[3]) : "r"(addr));
}
__device__ __forceinline__ void ldsm4t(unsigned* r, unsigned addr) {
    asm volatile("ldmatrix.sync.aligned.m8n8.x4.trans.shared.b16 {%0,%1,%2,%3}, [%4];"
                 : "=r"(r[0]), "=r"(r[1]), "=r"(r[2]), "=r"(r[3]) : "r"(addr));
}
__device__ __forceinline__ void cp16(unsigned dst, const void* src) {
    asm volatile("cp.async.cg.shared.global [%0], [%1], 16;" :: "r"(dst), "l"(src));
}
__device__ __forceinline__ unsigned pack_f16(float a, float b) {
    __half2 h = __floats2half2_rn(a, b);
    return *(unsigned*)&h;
}

// ======================= fp16 GEMM, 128x128 tile, cp.async 3-stage ==========
template <bool OUT_F16>
__global__ __launch_bounds__(256, 2) void gemm_f16(
    const uint4* __restrict__ A, const uint4* __restrict__ B, void* __restrict__ Cv,
    int K, int ldaG, int ldbG, int ldc)
{
    extern __shared__ uint4 smem[];
    uint4* sA = smem;           // [3][1024]
    uint4* sB = smem + 3072;    // [3][1024]

    const int tid = threadIdx.x, lane = tid & 31, wid = tid >> 5;
    const int wm = wid & 1, wn = wid >> 1, qr = lane >> 2, qc = lane & 3;
    const int grp = lane >> 3, lrow = lane & 7;
    const int bm0 = blockIdx.y * 128;
    const int bn0g = blockIdx.x * 16;
    const int NC = K / 64;

    const int cgA = tid & 7,  rowA0 = tid >> 3;
    const int cgB = tid & 15, rowB0 = tid >> 4;

    auto issue = [&](int c, int s) {
        const uint4* ag = A + (long)(bm0 + rowA0) * ldaG + c * 8 + cgA;
        uint4* ad = sA + s * 1024;
#pragma unroll
        for (int r = 0; r < 4; r++) {
            int row = rowA0 + r * 32;
            cp16(sptr(ad + row * 8 + (cgA ^ (row & 7))), ag + (long)r * 32 * ldaG);
        }
        const uint4* bg = B + (long)(c * 64 + rowB0) * ldbG + bn0g + cgB;
        uint4* bd = sB + s * 1024;
#pragma unroll
        for (int r = 0; r < 4; r++) {
            int row = rowB0 + r * 16;
            cp16(sptr(bd + row * 16 + (cgB ^ (row & 7))), bg + (long)r * 16 * ldbG);
        }
        asm volatile("cp.async.commit_group;");
    };

    issue(0, 0);
    if (NC > 1) issue(1, 1);
    if (NC > 2) issue(2, 2);

    float acc[4][4][4];
#pragma unroll
    for (int i = 0; i < 4; i++)
#pragma unroll
        for (int j = 0; j < 4; j++)
#pragma unroll
            for (int f = 0; f < 4; f++) acc[i][j][f] = 0.f;

    int s = 0;
#pragma unroll 1
    for (int c = 0; c < NC; c++) {
        asm volatile("cp.async.wait_group 2;");
        __syncthreads();
        const uint4* sAs = sA + s * 1024;
        const uint4* sBs = sB + s * 1024;

#pragma unroll
        for (int ks = 0; ks < 4; ks++) {
            unsigned af[4][4], bfr[2][4];
#pragma unroll
            for (int i = 0; i < 4; i++) {
                int row = wm * 64 + i * 16 + lrow + (grp & 1) * 8;
                int g = (2 * ks + (grp >> 1)) ^ (row & 7);
                ldsm4(af[i], sptr(sAs + row * 8 + g));
            }
#pragma unroll
            for (int jp = 0; jp < 2; jp++) {
                int brow = ks * 16 + (grp & 1) * 8 + lrow;
                int bg = (wn * 4 + jp * 2 + (grp >> 1)) ^ (brow & 7);
                ldsm4t(bfr[jp], sptr(sBs + brow * 16 + bg));
            }
#pragma unroll
            for (int i = 0; i < 4; i++)
#pragma unroll
                for (int jp = 0; jp < 2; jp++) {
                    mma_f16(acc[i][jp * 2 + 0], af[i], bfr[jp][0], bfr[jp][1]);
                    mma_f16(acc[i][jp * 2 + 1], af[i], bfr[jp][2], bfr[jp][3]);
                }
        }
        __syncthreads();
        if (c + 3 < NC) issue(c + 3, s);
        s = (s == 2) ? 0 : s + 1;
    }

#pragma unroll
    for (int i = 0; i < 4; i++) {
        long row = bm0 + wm * 64 + i * 16 + qr;
#pragma unroll
        for (int j = 0; j < 4; j++) {
            int col = bn0g * 8 + wn * 32 + j * 8 + 2 * qc;
            if (OUT_F16) {
                __half* C = (__half*)Cv;
                *(unsigned*)(C + row * ldc + col) = pack_f16(acc[i][j][0], acc[i][j][1]);
                *(unsigned*)(C + (row + 8) * ldc + col) = pack_f16(acc[i][j][2], acc[i][j][3]);
            } else {
                float* C = (float*)Cv;
                *(float2*)(C + row * ldc + col) = make_float2(acc[i][j][0], acc[i][j][1]);
                *(float2*)(C + (row + 8) * ldc + col) = make_float2(acc[i][j][2], acc[i][j][3]);
            }
        }
    }
}

// ============ fused fp32 -> fp16 convert (x, w_qkv, w_o) + zero Z/colsum ====
#define N_X  ((long)BS * HID / 8)        // 524288
#define N_WQ ((long)HID * F3 / 8)        // 393216
#define N_WO ((long)HID * HID / 8)       // 131072
#define N_CV (N_X + N_WQ + N_WO)
#define N_ZB ((long)NBH * SEQ / 4)       // 16384 float4 per accum array

__global__ __launch_bounds__(256) void cvt_all_kernel(
    const float4* __restrict__ x, const float4* __restrict__ wq,
    const float4* __restrict__ wo,
    uint4* __restrict__ x16, uint4* __restrict__ wq16, uint4* __restrict__ wo16,
    float4* __restrict__ z, float4* __restrict__ cs)
{
    long i = (long)blockIdx.x * 256 + threadIdx.x;
    if (i >= N_CV) {
        long j = i - N_CV;
        if (j < N_ZB) {
            float4 zero = make_float4(0.f, 0.f, 0.f, 0.f);
            z[j] = zero;
            cs[j] = zero;
        }
        return;
    }
    const float4* src;
    uint4* dst;
    long j;
    if (i < N_X)              { src = x;  dst = x16;  j = i; }
    else if (i < N_X + N_WQ)  { src = wq; dst = wq16; j = i - N_X; }
    else                      { src = wo; dst = wo16; j = i - N_X - N_WQ; }
    float4 v0 = src[2 * j], v1 = src[2 * j + 1];
    dst[j] = make_uint4(pack_f16(v0.x, v0.y), pack_f16(v0.z, v0.w),
                        pack_f16(v1.x, v1.y), pack_f16(v1.z, v1.w));
}

// ======================= qk pass 1: Z[q] += sum over 512 keys of exp(s) =====
// 1 q-block x 4 key-blocks per CTA (round-13 validated)
__global__ __launch_bounds__(256, 2) void qk1_kernel(
    const uint4* __restrict__ qkv16, float* __restrict__ Z)
{
    __shared__ uint4 Qs[1024];         // 16 KB
    __shared__ uint4 Ks[2][1024];      // 32 KB double buffer
    __shared__ float s_red[512];

    const int tid = threadIdx.x, lane = tid & 31, wid = tid >> 5;
    const int wm = wid & 1, wn = wid >> 1, qr = lane >> 2, qc = lane & 3;
    const int bz = blockIdx.z;
    const int b = bz >> 4, h = bz & 15;
    const int bm0 = blockIdx.y * 128;
    const int bn_base = blockIdx.x * 512;

    const uint4* Qg = qkv16 + (long)b * SEQ * 384 + h * 8;
    const uint4* Kg = Qg + 128;

    const int cg = tid & 7, rb = tid >> 3;

    {
        const uint4* qg = Qg + (long)(bm0 + rb) * 384 + cg;
#pragma unroll
        for (int r = 0; r < 4; r++) {
            int row = rb + r * 32;
            cp16(sptr(&Qs[row * 8 + (cg ^ (row & 7))]), qg + (long)r * 32 * 384);
        }
        const uint4* kg = Kg + (long)(bn_base + rb) * 384 + cg;
#pragma unroll
        for (int r = 0; r < 4; r++) {
            int row = rb + r * 32;
            cp16(sptr(&Ks[0][row * 8 + (cg ^ (row & 7))]), kg + (long)r * 32 * 384);
        }
        asm volatile("cp.async.commit_group;");
    }
    {
        const uint4* kg = Kg + (long)(bn_base + 128 + rb) * 384 + cg;
#pragma unroll
        for (int r = 0; r < 4; r++) {
            int row = rb + r * 32;
            cp16(sptr(&Ks[1][row * 8 + (cg ^ (row & 7))]), kg + (long)r * 32 * 384);
        }
        asm volatile("cp.async.commit_group;");
    }

    const int grp = lane >> 3, lrow = lane & 7;
    const int a_roff = (grp & 1) * 8, a_kg = grp >> 1;
    const int b_roff = (grp >> 1) * 8, b_kg = grp & 1;

    float lz[4][2];
#pragma unroll
    for (int i = 0; i < 4; i++)
#pragma unroll
        for (int h2 = 0; h2 < 2; h2++) lz[i][h2] = 0.f;

#pragma unroll 1
    for (int nb = 0; nb < 4; nb++) {
        if (nb < 3) asm volatile("cp.async.wait_group 1;");
        else        asm volatile("cp.async.wait_group 0;");
        __syncthreads();

        float acc[4][4][4];
#pragma unroll
        for (int i = 0; i < 4; i++)
#pragma unroll
            for (int j = 0; j < 4; j++)
#pragma unroll
                for (int f = 0; f < 4; f++) acc[i][j][f] = 0.f;

        const uint4* Kb = Ks[nb & 1];
#pragma unroll
        for (int g = 0; g < 4; g++) {
            unsigned af[4][4], bfr[2][4];
#pragma unroll
            for (int i = 0; i < 4; i++) {
                int row = wm * 64 + i * 16 + lrow + a_roff;
                int gr = (2 * g + a_kg) ^ (row & 7);
                ldsm4(af[i], sptr(&Qs[row * 8 + gr]));
            }
#pragma unroll
            for (int jp = 0; jp < 2; jp++) {
                int row = wn * 32 + jp * 16 + lrow + b_roff;
                int gr = (2 * g + b_kg) ^ (row & 7);
                ldsm4(bfr[jp], sptr(&Kb[row * 8 + gr]));
            }
#pragma unroll
            for (int i = 0; i < 4; i++)
#pragma unroll
                for (int jp = 0; jp < 2; jp++) {
                    mma_f16(acc[i][jp * 2 + 0], af[i], bfr[jp][0], bfr[jp][1]);
                    mma_f16(acc[i][jp * 2 + 1], af[i], bfr[jp][2], bfr[jp][3]);
                }
        }
        __syncthreads();

        if (nb + 2 < 4) {
            const uint4* kg = Kg + (long)(bn_base + (nb + 2) * 128 + rb) * 384 + cg;
            uint4* kd = Ks[nb & 1];
#pragma unroll
            for (int r = 0; r < 4; r++) {
                int row = rb + r * 32;
                cp16(sptr(&kd[row * 8 + (cg ^ (row & 7))]), kg + (long)r * 32 * 384);
            }
            asm volatile("cp.async.commit_group;");
        }

#pragma unroll
        for (int i = 0; i < 4; i++)
#pragma unroll
            for (int h2 = 0; h2 < 2; h2++) {
#pragma unroll
                for (int j = 0; j < 4; j++) {
                    lz[i][h2] += ex2f(acc[i][j][2 * h2]     * C2EXP);
                    lz[i][h2] += ex2f(acc[i][j][2 * h2 + 1] * C2EXP);
                }
            }
    }

#pragma unroll
    for (int d = 1; d <= 2; d <<= 1)
#pragma unroll
        for (int i = 0; i < 4; i++)
#pragma unroll
            for (int h2 = 0; h2 < 2; h2++)
                lz[i][h2] += __shfl_xor_sync(0xffffffffu, lz[i][h2], d);
    __syncthreads();
    if (qc == 0)
#pragma unroll
        for (int i = 0; i < 4; i++)
#pragma unroll
            for (int h2 = 0; h2 < 2; h2++)
                s_red[wn * 128 + wm * 64 + i * 16 + h2 * 8 + qr] = lz[i][h2];
    __syncthreads();
    if (tid < 128) {
        float z = s_red[tid] + s_red[128 + tid] + s_red[256 + tid] + s_red[384 + tid];
        atomicAdd(&Z[(long)bz * SEQ + bm0 + tid], z);
    }
}

// ======================= qk pass 2 (transposed): K resident, Q streamed =====
// CTA: one key-block (128 cols) x one q-strip (512 rows = 4 tiles).
__global__ __launch_bounds__(256, 2) void qk2_kernel(
    const uint4* __restrict__ qkv16, const float* __restrict__ Z,
    float* __restrict__ colsum)
{
    extern __shared__ uint4 dsm[];
    uint4* Ks   = dsm;               // 1024 granules (16 KB), resident
    uint4* Qs   = dsm + 1024;        // 2 x 1024 granules (32 KB) double buffer
    float* s_iz = (float*)(dsm + 3072);   // 512 floats (strip 1/Z)
    float* s_red = s_iz + 512;            // 256 floats

    const int tid = threadIdx.x, lane = tid & 31, wid = tid >> 5;
    const int wm = wid & 1, wn = wid >> 1, qr = lane >> 2, qc = lane & 3;
    const int bz = blockIdx.z;
    const int b = bz >> 4, h = bz & 15;
    const int kb0 = blockIdx.x * 128;
    const int q0  = blockIdx.y * (SEQ / QSTRIPS);     // 512-row strip

    const uint4* Qg = qkv16 + (long)b * SEQ * 384 + h * 8;
    const uint4* Kg = Qg + 128;

    const int cg = tid & 7, rb = tid >> 3;

    // K tile + Q tile 0
    {
        const uint4* kg = Kg + (long)(kb0 + rb) * 384 + cg;
#pragma unroll
        for (int r = 0; r < 4; r++) {
            int row = rb + r * 32;
            cp16(sptr(&Ks[row * 8 + (cg ^ (row & 7))]), kg + (long)r * 32 * 384);
        }
        const uint4* qg = Qg + (long)(q0 + rb) * 384 + cg;
#pragma unroll
        for (int r = 0; r < 4; r++) {
            int row = rb + r * 32;
            cp16(sptr(&Qs[row * 8 + (cg ^ (row & 7))]), qg + (long)r * 32 * 384);
        }
        asm volatile("cp.async.commit_group;");
    }
    // Q tile 1
    {
        const uint4* qg = Qg + (long)(q0 + 128 + rb) * 384 + cg;
#pragma unroll
        for (int r = 0; r < 4; r++) {
            int row = rb + r * 32;
            cp16(sptr(&Qs[1024 + row * 8 + (cg ^ (row & 7))]), qg + (long)r * 32 * 384);
        }
        asm volatile("cp.async.commit_group;");
    }

    // stage 1/Z for the strip (2 values per thread)
#pragma unroll
    for (int r = 0; r < 2; r++) {
        int idx = tid + r * 256;
        s_iz[idx] = 1.0f / Z[(long)bz * SEQ + q0 + idx];
    }

    const int grp = lane >> 3, lrow = lane & 7;
    const int a_roff = (grp & 1) * 8, a_kg = grp >> 1;
    const int b_roff = (grp >> 1) * 8, b_kg = grp & 1;

    float cs[4][2];
#pragma unroll
    for (int j = 0; j < 4; j++) { cs[j][0] = 0.f; cs[j][1] = 0.f; }

#pragma unroll 1
    for (int qt = 0; qt < 4; qt++) {
        if (qt < 3) asm volatile("cp.async.wait_group 1;");
        else        asm volatile("cp.async.wait_group 0;");
        __syncthreads();

        float izreg[4][2];
#pragma unroll
        for (int i = 0; i < 4; i++)
#pragma unroll
            for (int h2 = 0; h2 < 2; h2++)
                izreg[i][h2] = s_iz[qt * 128 + wm * 64 + i * 16 + h2 * 8 + qr];

        float acc[4][4][4];
#pragma unroll
        for (int i = 0; i < 4; i++)
#pragma unroll
            for (int j = 0; j < 4; j++)
#pragma unroll
                for (int f = 0; f < 4; f++) acc[i][j][f] = 0.f;

        const uint4* Qb = Qs + (qt & 1) * 1024;
#pragma unroll
        for (int g = 0; g < 4; g++) {
            unsigned af[4][4], bfr[2][4];
#pragma unroll
            for (int i = 0; i < 4; i++) {
                int row = wm * 64 + i * 16 + lrow + a_roff;
                int gr = (2 * g + a_kg) ^ (row & 7);
                ldsm4(af[i], sptr(&Qb[row * 8 + gr]));
            }
#pragma unroll
            for (int jp = 0; jp < 2; jp++) {
                int row = wn * 32 + jp * 16 + lrow + b_roff;
                int gr = (2 * g + b_kg) ^ (row & 7);
                ldsm4(bfr[jp], sptr(&Ks[row * 8 + gr]));
            }
#pragma unroll
            for (int i = 0; i < 4; i++)
#pragma unroll
                for (int jp = 0; jp < 2; jp++) {
                    mma_f16(acc[i][jp * 2 + 0], af[i], bfr[jp][0], bfr[jp][1]);
                    mma_f16(acc[i][jp * 2 + 1], af[i], bfr[jp][2], bfr[jp][3]);
                }
        }
        __syncthreads();

        // prefetch Q tile qt+2 into freed buffer
        if (qt + 2 < 4) {
            const uint4* qg = Qg + (long)(q0 + (qt + 2) * 128 + rb) * 384 + cg;
            uint4* qd = Qs + (qt & 1) * 1024;
#pragma unroll
            for (int r = 0; r < 4; r++) {
                int row = rb + r * 32;
                cp16(sptr(&qd[row * 8 + (cg ^ (row & 7))]), qg + (long)r * 32 * 384);
            }
            asm volatile("cp.async.commit_group;");
        }

#pragma unroll
        for (int i = 0; i < 4; i++)
#pragma unroll
            for (int h2 = 0; h2 < 2; h2++) {
                float iz = izreg[i][h2];
#pragma unroll
                for (int j = 0; j < 4; j++) {
                    cs[j][0] += ex2f(acc[i][j][2 * h2]     * C2EXP) * iz;
                    cs[j][1] += ex2f(acc[i][j][2 * h2 + 1] * C2EXP) * iz;
                }
            }
    }

    // reduce over qr lanes, combine the two wm warps, one atomic per column
#pragma unroll
    for (int d = 4; d <= 16; d <<= 1)
#pragma unroll
        for (int j = 0; j < 4; j++) {
            cs[j][0] += __shfl_xor_sync(0xffffffffu, cs[j][0], d);
            cs[j][1] += __shfl_xor_sync(0xffffffffu, cs[j][1], d);
        }
    if (qr == 0) {
#pragma unroll
        for (int j = 0; j < 4; j++) {
            s_red[wm * 128 + wn * 32 + j * 8 + 2 * qc]     = cs[j][0];
            s_red[wm * 128 + wn * 32 + j * 8 + 2 * qc + 1] = cs[j][1];
        }
    }
    __syncthreads();
    if (tid < 128) {
        float v = s_red[tid] + s_red[128 + tid];
        atomicAdd(&colsum[(long)bz * SEQ + kb0 + tid], v);
    }
}

// ======================= v * colsum -> fp16 vals ============================
__global__ __launch_bounds__(256) void scale_v16_kernel(
    const uint4* __restrict__ qkv16, const float* __restrict__ cs,
    uint4* __restrict__ vals16)
{
    long i = (long)blockIdx.x * 256 + threadIdx.x;
    long bs = i >> 7;
    int fg = (int)(i & 127);
    int h = fg >> 3;
    int b = (int)(bs >> 11), s = (int)(bs & (SEQ - 1));
    float sc = cs[(((long)b << 4) + h) * SEQ + s];
    uint4 v = qkv16[bs * 384 + 256 + fg];
    uint4 o;
    unsigned* vp = (unsigned*)&v;
    unsigned* op = (unsigned*)&o;
#pragma unroll
    for (int j = 0; j < 4; j++) {
        float2 f = __half22float2(*(__half2*)&vp[j]);
        op[j] = pack_f16(f.x * sc, f.y * sc);
    }
    vals16[i] = o;
}

// ---------------- launcher --------------------------------------------------
#define GEMM_SMEM 98304
#define QK2_SMEM  (49152 + 2048 + 1024 + 128)   // Ks+Qs + s_iz(512) + s_red

extern "C" void kernel_launch(void* const* d_in, const int* in_sizes, int n_in,
                              void* d_out, int out_size)
{
    const float* x     = (const float*)d_in[0];
    const float* w_qkv = (const float*)d_in[1];
    const float* w_o   = (const float*)d_in[2];
    float* out = (float*)d_out;

    float *p_z, *p_cs;
    uint4 *p_qkv16, *p_x16, *p_wq16, *p_wo16, *p_vals16;
    cudaGetSymbolAddress((void**)&p_z,      g_z);
    cudaGetSymbolAddress((void**)&p_cs,     g_colsum);
    cudaGetSymbolAddress((void**)&p_qkv16,  g_qkv16);
    cudaGetSymbolAddress((void**)&p_x16,    g_x16);
    cudaGetSymbolAddress((void**)&p_wq16,   g_wq16);
    cudaGetSymbolAddress((void**)&p_wo16,   g_wo16);
    cudaGetSymbolAddress((void**)&p_vals16, g_vals16);

    cudaFuncSetAttribute(gemm_f16<true>,  cudaFuncAttributeMaxDynamicSharedMemorySize, GEMM_SMEM);
    cudaFuncSetAttribute(gemm_f16<false>, cudaFuncAttributeMaxDynamicSharedMemorySize, GEMM_SMEM);
    cudaFuncSetAttribute(qk2_kernel, cudaFuncAttributeMaxDynamicSharedMemorySize, QK2_SMEM);

    dim3 blk(256);

    // 0. convert inputs to fp16 + zero Z/colsum (one kernel)
    cvt_all_kernel<<<(int)((N_CV + N_ZB + 255) / 256), blk>>>(
        (const float4*)x, (const float4*)w_qkv, (const float4*)w_o,
        p_x16, p_wq16, p_wo16, (float4*)p_z, (float4*)p_cs);

    // 1. qkv(fp16) = x16 @ wq16
    gemm_f16<true><<<dim3(F3 / 128, BS / 128), blk, GEMM_SMEM>>>(
        p_x16, p_wq16, p_qkv16, HID, HID / 8, F3 / 8, F3);

    // 2. pass 1: Z[q] = sum_k exp(q.k/8)
    qk1_kernel<<<dim3(SEQ / 512, SEQ / 128, NBH), blk>>>(p_qkv16, p_z);

    // 3. pass 2 (transposed): colsum[k] = sum_q exp(q.k/8)/Z[q]
    qk2_kernel<<<dim3(SEQ / 128, QSTRIPS, NBH), blk, QK2_SMEM>>>(p_qkv16, p_z, p_cs);

    // 4. vals16 = fp16(v * colsum)
    scale_v16_kernel<<<(int)(((long)BS * HID / 8) / 256), blk>>>(p_qkv16, p_cs, p_vals16);

    // 5. out(fp32) = vals16 @ wo16
    gemm_f16<false><<<dim3(HID / 128, BS / 128), blk, GEMM_SMEM>>>(
        p_vals16, p_wo16, out, HID, HID / 8, HID / 8, HID);
}

// round 17
// speedup vs baseline: 1.0904x; 1.0443x over previous
#include <cuda_runtime.h>
#include <cuda_fp16.h>
#include <math.h>

#define BATCH 2
#define SEQ   2048
#define NH    16
#define HD    64
#define HID   1024
#define F3    3072
#define BS    (BATCH*SEQ)
#define NBH   (BATCH*NH)        // 32
#define QSTRIPS 4               // q-strips in qk2 (each 512 rows = 4 tiles)

// 0.125 * log2(e) — folded into q-columns of w_qkv at conversion time
#define C2EXP 0.1803368801111204f

// ---------------- scratch (device globals) ---------------------------------
__device__ uint4 g_qkv16[(size_t)BS * F3 / 8];           // fp16 qkv, 25.2 MB
__device__ uint4 g_x16[(size_t)BS * HID / 8];            // fp16 x
__device__ uint4 g_wq16[(size_t)HID * F3 / 8];           // fp16 w_qkv (q cols pre-scaled)
__device__ uint4 g_wo16[(size_t)HID * HID / 8];          // fp16 w_o
__device__ uint4 g_vals16[(size_t)BS * HID / 8];         // fp16 v*colsum
__device__ float g_z[NBH * SEQ];
__device__ float g_colsum[NBH * SEQ];

__device__ __forceinline__ float ex2f(float x) {
    float r; asm("ex2.approx.f32 %0, %1;" : "=f"(r) : "f"(x)); return r;
}
__device__ __forceinline__ unsigned sptr(const void* p) {
    return (unsigned)__cvta_generic_to_shared(p);
}
__device__ __forceinline__ void mma_f16(float* c, const unsigned* a, unsigned b0, unsigned b1) {
    asm volatile(
        "mma.sync.aligned.m16n8k16.row.col.f32.f16.f16.f32 "
        "{%0,%1,%2,%3}, {%4,%5,%6,%7}, {%8,%9}, {%0,%1,%2,%3};"
        : "+f"(c[0]), "+f"(c[1]), "+f"(c[2]), "+f"(c[3])
        : "r"(a[0]), "r"(a[1]), "r"(a[2]), "r"(a[3]), "r"(b0), "r"(b1));
}
__device__ __forceinline__ void ldsm4(unsigned* r, unsigned addr) {
    asm volatile("ldmatrix.sync.aligned.m8n8.x4.shared.b16 {%0,%1,%2,%3}, [%4];"
                 : "=r"(r[0]), "=r"(r[1]), "=r"(r[2]), "=r"(r[3]) : "r"(addr));
}
__device__ __forceinline__ void ldsm4t(unsigned* r, unsigned addr) {
    asm volatile("ldmatrix.sync.aligned.m8n8.x4.trans.shared.b16 {%0,%1,%2,%3}, [%4];"
                 : "=r"(r[0]), "=r"(r[1]), "=r"(r[2]), "=r"(r[3]) : "r"(addr));
}
__device__ __forceinline__ void cp16(unsigned dst, const void* src) {
    asm volatile("cp.async.cg.shared.global [%0], [%1], 16;" :: "r"(dst), "l"(src));
}
__device__ __forceinline__ unsigned pack_f16(float a, float b) {
    __half2 h = __floats2half2_rn(a, b);
    return *(unsigned*)&h;
}

// ======================= fp16 GEMM, 128x128 tile, cp.async 3-stage ==========
template <bool OUT_F16>
__global__ __launch_bounds__(256, 2) void gemm_f16(
    const uint4* __restrict__ A, const uint4* __restrict__ B, void* __restrict__ Cv,
    int K, int ldaG, int ldbG, int ldc)
{
    extern __shared__ uint4 smem[];
    uint4* sA = smem;           // [3][1024]
    uint4* sB = smem + 3072;    // [3][1024]

    const int tid = threadIdx.x, lane = tid & 31, wid = tid >> 5;
    const int wm = wid & 1, wn = wid >> 1, qr = lane >> 2, qc = lane & 3;
    const int grp = lane >> 3, lrow = lane & 7;
    const int bm0 = blockIdx.y * 128;
    const int bn0g = blockIdx.x * 16;
    const int NC = K / 64;

    const int cgA = tid & 7,  rowA0 = tid >> 3;
    const int cgB = tid & 15, rowB0 = tid >> 4;

    auto issue = [&](int c, int s) {
        const uint4* ag = A + (long)(bm0 + rowA0) * ldaG + c * 8 + cgA;
        uint4* ad = sA + s * 1024;
#pragma unroll
        for (int r = 0; r < 4; r++) {
            int row = rowA0 + r * 32;
            cp16(sptr(ad + row * 8 + (cgA ^ (row & 7))), ag + (long)r * 32 * ldaG);
        }
        const uint4* bg = B + (long)(c * 64 + rowB0) * ldbG + bn0g + cgB;
        uint4* bd = sB + s * 1024;
#pragma unroll
        for (int r = 0; r < 4; r++) {
            int row = rowB0 + r * 16;
            cp16(sptr(bd + row * 16 + (cgB ^ (row & 7))), bg + (long)r * 16 * ldbG);
        }
        asm volatile("cp.async.commit_group;");
    };

    issue(0, 0);
    if (NC > 1) issue(1, 1);
    if (NC > 2) issue(2, 2);

    float acc[4][4][4];
#pragma unroll
    for (int i = 0; i < 4; i++)
#pragma unroll
        for (int j = 0; j < 4; j++)
#pragma unroll
            for (int f = 0; f < 4; f++) acc[i][j][f] = 0.f;

    int s = 0;
#pragma unroll 1
    for (int c = 0; c < NC; c++) {
        asm volatile("cp.async.wait_group 2;");
        __syncthreads();
        const uint4* sAs = sA + s * 1024;
        const uint4* sBs = sB + s * 1024;

#pragma unroll
        for (int ks = 0; ks < 4; ks++) {
            unsigned af[4][4], bfr[2][4];
#pragma unroll
            for (int i = 0; i < 4; i++) {
                int row = wm * 64 + i * 16 + lrow + (grp & 1) * 8;
                int g = (2 * ks + (grp >> 1)) ^ (row & 7);
                ldsm4(af[i], sptr(sAs + row * 8 + g));
            }
#pragma unroll
            for (int jp = 0; jp < 2; jp++) {
                int brow = ks * 16 + (grp & 1) * 8 + lrow;
                int bg = (wn * 4 + jp * 2 + (grp >> 1)) ^ (brow & 7);
                ldsm4t(bfr[jp], sptr(sBs + brow * 16 + bg));
            }
#pragma unroll
            for (int i = 0; i < 4; i++)
#pragma unroll
                for (int jp = 0; jp < 2; jp++) {
                    mma_f16(acc[i][jp * 2 + 0], af[i], bfr[jp][0], bfr[jp][1]);
                    mma_f16(acc[i][jp * 2 + 1], af[i], bfr[jp][2], bfr[jp][3]);
                }
        }
        __syncthreads();
        if (c + 3 < NC) issue(c + 3, s);
        s = (s == 2) ? 0 : s + 1;
    }

#pragma unroll
    for (int i = 0; i < 4; i++) {
        long row = bm0 + wm * 64 + i * 16 + qr;
#pragma unroll
        for (int j = 0; j < 4; j++) {
            int col = bn0g * 8 + wn * 32 + j * 8 + 2 * qc;
            if (OUT_F16) {
                __half* C = (__half*)Cv;
                *(unsigned*)(C + row * ldc + col) = pack_f16(acc[i][j][0], acc[i][j][1]);
                *(unsigned*)(C + (row + 8) * ldc + col) = pack_f16(acc[i][j][2], acc[i][j][3]);
            } else {
                float* C = (float*)Cv;
                *(float2*)(C + row * ldc + col) = make_float2(acc[i][j][0], acc[i][j][1]);
                *(float2*)(C + (row + 8) * ldc + col) = make_float2(acc[i][j][2], acc[i][j][3]);
            }
        }
    }
}

// ============ fused fp32 -> fp16 convert (x, w_qkv, w_o) + zero Z/colsum ====
// q-columns (col < 1024) of w_qkv are pre-scaled by C2EXP so qk scores land
// directly in log2 domain (saves one FMUL per score element in both qk passes).
#define N_X  ((long)BS * HID / 8)        // 524288
#define N_WQ ((long)HID * F3 / 8)        // 393216
#define N_WO ((long)HID * HID / 8)       // 131072
#define N_CV (N_X + N_WQ + N_WO)
#define N_ZB ((long)NBH * SEQ / 4)       // 16384 float4 per accum array

__global__ __launch_bounds__(256) void cvt_all_kernel(
    const float4* __restrict__ x, const float4* __restrict__ wq,
    const float4* __restrict__ wo,
    uint4* __restrict__ x16, uint4* __restrict__ wq16, uint4* __restrict__ wo16,
    float4* __restrict__ z, float4* __restrict__ cs)
{
    long i = (long)blockIdx.x * 256 + threadIdx.x;
    if (i >= N_CV) {
        long j = i - N_CV;
        if (j < N_ZB) {
            float4 zero = make_float4(0.f, 0.f, 0.f, 0.f);
            z[j] = zero;
            cs[j] = zero;
        }
        return;
    }
    const float4* src;
    uint4* dst;
    long j;
    float sc = 1.0f;
    if (i < N_X)              { src = x;  dst = x16;  j = i; }
    else if (i < N_X + N_WQ)  {
        src = wq; dst = wq16; j = i - N_X;
        int colg = (int)(j % (F3 / 8));          // granule column within row
        if (colg < HID / 8) sc = C2EXP;          // q-columns only
    }
    else                      { src = wo; dst = wo16; j = i - N_X - N_WQ; }
    float4 v0 = src[2 * j], v1 = src[2 * j + 1];
    v0.x *= sc; v0.y *= sc; v0.z *= sc; v0.w *= sc;
    v1.x *= sc; v1.y *= sc; v1.z *= sc; v1.w *= sc;
    dst[j] = make_uint4(pack_f16(v0.x, v0.y), pack_f16(v0.z, v0.w),
                        pack_f16(v1.x, v1.y), pack_f16(v1.z, v1.w));
}

// ======================= qk pass 1: Z[q] += sum over 512 keys of 2^s ========
__global__ __launch_bounds__(256, 2) void qk1_kernel(
    const uint4* __restrict__ qkv16, float* __restrict__ Z)
{
    __shared__ uint4 Qs[1024];         // 16 KB
    __shared__ uint4 Ks[2][1024];      // 32 KB double buffer
    __shared__ float s_red[512];

    const int tid = threadIdx.x, lane = tid & 31, wid = tid >> 5;
    const int wm = wid & 1, wn = wid >> 1, qr = lane >> 2, qc = lane & 3;
    const int bz = blockIdx.z;
    const int b = bz >> 4, h = bz & 15;
    const int bm0 = blockIdx.y * 128;
    const int bn_base = blockIdx.x * 512;

    const uint4* Qg = qkv16 + (long)b * SEQ * 384 + h * 8;
    const uint4* Kg = Qg + 128;

    const int cg = tid & 7, rb = tid >> 3;

    {
        const uint4* qg = Qg + (long)(bm0 + rb) * 384 + cg;
#pragma unroll
        for (int r = 0; r < 4; r++) {
            int row = rb + r * 32;
            cp16(sptr(&Qs[row * 8 + (cg ^ (row & 7))]), qg + (long)r * 32 * 384);
        }
        const uint4* kg = Kg + (long)(bn_base + rb) * 384 + cg;
#pragma unroll
        for (int r = 0; r < 4; r++) {
            int row = rb + r * 32;
            cp16(sptr(&Ks[0][row * 8 + (cg ^ (row & 7))]), kg + (long)r * 32 * 384);
        }
        asm volatile("cp.async.commit_group;");
    }
    {
        const uint4* kg = Kg + (long)(bn_base + 128 + rb) * 384 + cg;
#pragma unroll
        for (int r = 0; r < 4; r++) {
            int row = rb + r * 32;
            cp16(sptr(&Ks[1][row * 8 + (cg ^ (row & 7))]), kg + (long)r * 32 * 384);
        }
        asm volatile("cp.async.commit_group;");
    }

    const int grp = lane >> 3, lrow = lane & 7;
    const int a_roff = (grp & 1) * 8, a_kg = grp >> 1;
    const int b_roff = (grp >> 1) * 8, b_kg = grp & 1;

    float lz[4][2];
#pragma unroll
    for (int i = 0; i < 4; i++)
#pragma unroll
        for (int h2 = 0; h2 < 2; h2++) lz[i][h2] = 0.f;

#pragma unroll 1
    for (int nb = 0; nb < 4; nb++) {
        if (nb < 3) asm volatile("cp.async.wait_group 1;");
        else        asm volatile("cp.async.wait_group 0;");
        __syncthreads();

        float acc[4][4][4];
#pragma unroll
        for (int i = 0; i < 4; i++)
#pragma unroll
            for (int j = 0; j < 4; j++)
#pragma unroll
                for (int f = 0; f < 4; f++) acc[i][j][f] = 0.f;

        const uint4* Kb = Ks[nb & 1];
#pragma unroll
        for (int g = 0; g < 4; g++) {
            unsigned af[4][4], bfr[2][4];
#pragma unroll
            for (int i = 0; i < 4; i++) {
                int row = wm * 64 + i * 16 + lrow + a_roff;
                int gr = (2 * g + a_kg) ^ (row & 7);
                ldsm4(af[i], sptr(&Qs[row * 8 + gr]));
            }
#pragma unroll
            for (int jp = 0; jp < 2; jp++) {
                int row = wn * 32 + jp * 16 + lrow + b_roff;
                int gr = (2 * g + b_kg) ^ (row & 7);
                ldsm4(bfr[jp], sptr(&Kb[row * 8 + gr]));
            }
#pragma unroll
            for (int i = 0; i < 4; i++)
#pragma unroll
                for (int jp = 0; jp < 2; jp++) {
                    mma_f16(acc[i][jp * 2 + 0], af[i], bfr[jp][0], bfr[jp][1]);
                    mma_f16(acc[i][jp * 2 + 1], af[i], bfr[jp][2], bfr[jp][3]);
                }
        }
        __syncthreads();

        if (nb + 2 < 4) {
            const uint4* kg = Kg + (long)(bn_base + (nb + 2) * 128 + rb) * 384 + cg;
            uint4* kd = Ks[nb & 1];
#pragma unroll
            for (int r = 0; r < 4; r++) {
                int row = rb + r * 32;
                cp16(sptr(&kd[row * 8 + (cg ^ (row & 7))]), kg + (long)r * 32 * 384);
            }
            asm volatile("cp.async.commit_group;");
        }

#pragma unroll
        for (int i = 0; i < 4; i++)
#pragma unroll
            for (int h2 = 0; h2 < 2; h2++) {
#pragma unroll
                for (int j = 0; j < 4; j++) {
                    lz[i][h2] += ex2f(acc[i][j][2 * h2]);
                    lz[i][h2] += ex2f(acc[i][j][2 * h2 + 1]);
                }
            }
    }

#pragma unroll
    for (int d = 1; d <= 2; d <<= 1)
#pragma unroll
        for (int i = 0; i < 4; i++)
#pragma unroll
            for (int h2 = 0; h2 < 2; h2++)
                lz[i][h2] += __shfl_xor_sync(0xffffffffu, lz[i][h2], d);
    __syncthreads();
    if (qc == 0)
#pragma unroll
        for (int i = 0; i < 4; i++)
#pragma unroll
            for (int h2 = 0; h2 < 2; h2++)
                s_red[wn * 128 + wm * 64 + i * 16 + h2 * 8 + qr] = lz[i][h2];
    __syncthreads();
    if (tid < 128) {
        float z = s_red[tid] + s_red[128 + tid] + s_red[256 + tid] + s_red[384 + tid];
        atomicAdd(&Z[(long)bz * SEQ + bm0 + tid], z);
    }
}

// ======================= qk pass 2 (transposed): K resident, Q streamed =====
__global__ __launch_bounds__(256, 2) void qk2_kernel(
    const uint4* __restrict__ qkv16, const float* __restrict__ Z,
    float* __restrict__ colsum)
{
    extern __shared__ uint4 dsm[];
    uint4* Ks   = dsm;               // 1024 granules (16 KB), resident
    uint4* Qs   = dsm + 1024;        // 2 x 1024 granules (32 KB) double buffer
    float* s_iz = (float*)(dsm + 3072);   // 512 floats (strip 1/Z)
    float* s_red = s_iz + 512;            // 256 floats

    const int tid = threadIdx.x, lane = tid & 31, wid = tid >> 5;
    const int wm = wid & 1, wn = wid >> 1, qr = lane >> 2, qc = lane & 3;
    const int bz = blockIdx.z;
    const int b = bz >> 4, h = bz & 15;
    const int kb0 = blockIdx.x * 128;
    const int q0  = blockIdx.y * (SEQ / QSTRIPS);     // 512-row strip

    const uint4* Qg = qkv16 + (long)b * SEQ * 384 + h * 8;
    const uint4* Kg = Qg + 128;

    const int cg = tid & 7, rb = tid >> 3;

    // K tile + Q tile 0
    {
        const uint4* kg = Kg + (long)(kb0 + rb) * 384 + cg;
#pragma unroll
        for (int r = 0; r < 4; r++) {
            int row = rb + r * 32;
            cp16(sptr(&Ks[row * 8 + (cg ^ (row & 7))]), kg + (long)r * 32 * 384);
        }
        const uint4* qg = Qg + (long)(q0 + rb) * 384 + cg;
#pragma unroll
        for (int r = 0; r < 4; r++) {
            int row = rb + r * 32;
            cp16(sptr(&Qs[row * 8 + (cg ^ (row & 7))]), qg + (long)r * 32 * 384);
        }
        asm volatile("cp.async.commit_group;");
    }
    // Q tile 1
    {
        const uint4* qg = Qg + (long)(q0 + 128 + rb) * 384 + cg;
#pragma unroll
        for (int r = 0; r < 4; r++) {
            int row = rb + r * 32;
            cp16(sptr(&Qs[1024 + row * 8 + (cg ^ (row & 7))]), qg + (long)r * 32 * 384);
        }
        asm volatile("cp.async.commit_group;");
    }

    // stage 1/Z for the strip (2 values per thread)
#pragma unroll
    for (int r = 0; r < 2; r++) {
        int idx = tid + r * 256;
        s_iz[idx] = 1.0f / Z[(long)bz * SEQ + q0 + idx];
    }

    const int grp = lane >> 3, lrow = lane & 7;
    const int a_roff = (grp & 1) * 8, a_kg = grp >> 1;
    const int b_roff = (grp >> 1) * 8, b_kg = grp & 1;

    float cs[4][2];
#pragma unroll
    for (int j = 0; j < 4; j++) { cs[j][0] = 0.f; cs[j][1] = 0.f; }

#pragma unroll 1
    for (int qt = 0; qt < 4; qt++) {
        if (qt < 3) asm volatile("cp.async.wait_group 1;");
        else        asm volatile("cp.async.wait_group 0;");
        __syncthreads();

        float izreg[4][2];
#pragma unroll
        for (int i = 0; i < 4; i++)
#pragma unroll
            for (int h2 = 0; h2 < 2; h2++)
                izreg[i][h2] = s_iz[qt * 128 + wm * 64 + i * 16 + h2 * 8 + qr];

        float acc[4][4][4];
#pragma unroll
        for (int i = 0; i < 4; i++)
#pragma unroll
            for (int j = 0; j < 4; j++)
#pragma unroll
                for (int f = 0; f < 4; f++) acc[i][j][f] = 0.f;

        const uint4* Qb = Qs + (qt & 1) * 1024;
#pragma unroll
        for (int g = 0; g < 4; g++) {
            unsigned af[4][4], bfr[2][4];
#pragma unroll
            for (int i = 0; i < 4; i++) {
                int row = wm * 64 + i * 16 + lrow + a_roff;
                int gr = (2 * g + a_kg) ^ (row & 7);
                ldsm4(af[i], sptr(&Qb[row * 8 + gr]));
            }
#pragma unroll
            for (int jp = 0; jp < 2; jp++) {
                int row = wn * 32 + jp * 16 + lrow + b_roff;
                int gr = (2 * g + b_kg) ^ (row & 7);
                ldsm4(bfr[jp], sptr(&Ks[row * 8 + gr]));
            }
#pragma unroll
            for (int i = 0; i < 4; i++)
#pragma unroll
                for (int jp = 0; jp < 2; jp++) {
                    mma_f16(acc[i][jp * 2 + 0], af[i], bfr[jp][0], bfr[jp][1]);
                    mma_f16(acc[i][jp * 2 + 1], af[i], bfr[jp][2], bfr[jp][3]);
                }
        }
        __syncthreads();

        if (qt + 2 < 4) {
            const uint4* qg = Qg + (long)(q0 + (qt + 2) * 128 + rb) * 384 + cg;
            uint4* qd = Qs + (qt & 1) * 1024;
#pragma unroll
            for (int r = 0; r < 4; r++) {
                int row = rb + r * 32;
                cp16(sptr(&qd[row * 8 + (cg ^ (row & 7))]), qg + (long)r * 32 * 384);
            }
            asm volatile("cp.async.commit_group;");
        }

#pragma unroll
        for (int i = 0; i < 4; i++)
#pragma unroll
            for (int h2 = 0; h2 < 2; h2++) {
                float iz = izreg[i][h2];
#pragma unroll
                for (int j = 0; j < 4; j++) {
                    cs[j][0] += ex2f(acc[i][j][2 * h2])     * iz;
                    cs[j][1] += ex2f(acc[i][j][2 * h2 + 1]) * iz;
                }
            }
    }

#pragma unroll
    for (int d = 4; d <= 16; d <<= 1)
#pragma unroll
        for (int j = 0; j < 4; j++) {
            cs[j][0] += __shfl_xor_sync(0xffffffffu, cs[j][0], d);
            cs[j][1] += __shfl_xor_sync(0xffffffffu, cs[j][1], d);
        }
    if (qr == 0) {
#pragma unroll
        for (int j = 0; j < 4; j++) {
            s_red[wm * 128 + wn * 32 + j * 8 + 2 * qc]     = cs[j][0];
            s_red[wm * 128 + wn * 32 + j * 8 + 2 * qc + 1] = cs[j][1];
        }
    }
    __syncthreads();
    if (tid < 128) {
        float v = s_red[tid] + s_red[128 + tid];
        atomicAdd(&colsum[(long)bz * SEQ + kb0 + tid], v);
    }
}

// ======================= v * colsum -> fp16 vals ============================
__global__ __launch_bounds__(256) void scale_v16_kernel(
    const uint4* __restrict__ qkv16, const float* __restrict__ cs,
    uint4* __restrict__ vals16)
{
    long i = (long)blockIdx.x * 256 + threadIdx.x;
    long bs = i >> 7;
    int fg = (int)(i & 127);
    int h = fg >> 3;
    int b = (int)(bs >> 11), s = (int)(bs & (SEQ - 1));
    float sc = cs[(((long)b << 4) + h) * SEQ + s];
    uint4 v = qkv16[bs * 384 + 256 + fg];
    uint4 o;
    unsigned* vp = (unsigned*)&v;
    unsigned* op = (unsigned*)&o;
#pragma unroll
    for (int j = 0; j < 4; j++) {
        float2 f = __half22float2(*(__half2*)&vp[j]);
        op[j] = pack_f16(f.x * sc, f.y * sc);
    }
    vals16[i] = o;
}

// ---------------- launcher --------------------------------------------------
#define GEMM_SMEM 98304
#define QK2_SMEM  (49152 + 2048 + 1024 + 128)   // Ks+Qs + s_iz(512) + s_red

extern "C" void kernel_launch(void* const* d_in, const int* in_sizes, int n_in,
                              void* d_out, int out_size)
{
    const float* x     = (const float*)d_in[0];
    const float* w_qkv = (const float*)d_in[1];
    const float* w_o   = (const float*)d_in[2];
    float* out = (float*)d_out;

    float *p_z, *p_cs;
    uint4 *p_qkv16, *p_x16, *p_wq16, *p_wo16, *p_vals16;
    cudaGetSymbolAddress((void**)&p_z,      g_z);
    cudaGetSymbolAddress((void**)&p_cs,     g_colsum);
    cudaGetSymbolAddress((void**)&p_qkv16,  g_qkv16);
    cudaGetSymbolAddress((void**)&p_x16,    g_x16);
    cudaGetSymbolAddress((void**)&p_wq16,   g_wq16);
    cudaGetSymbolAddress((void**)&p_wo16,   g_wo16);
    cudaGetSymbolAddress((void**)&p_vals16, g_vals16);

    cudaFuncSetAttribute(gemm_f16<true>,  cudaFuncAttributeMaxDynamicSharedMemorySize, GEMM_SMEM);
    cudaFuncSetAttribute(gemm_f16<false>, cudaFuncAttributeMaxDynamicSharedMemorySize, GEMM_SMEM);
    cudaFuncSetAttribute(qk2_kernel, cudaFuncAttributeMaxDynamicSharedMemorySize, QK2_SMEM);

    dim3 blk(256);

    // 0. convert inputs to fp16 (q-cols of w_qkv pre-scaled) + zero Z/colsum
    cvt_all_kernel<<<(int)((N_CV + N_ZB + 255) / 256), blk>>>(
        (const float4*)x, (const float4*)w_qkv, (const float4*)w_o,
        p_x16, p_wq16, p_wo16, (float4*)p_z, (float4*)p_cs);

    // 1. qkv(fp16) = x16 @ wq16
    gemm_f16<true><<<dim3(F3 / 128, BS / 128), blk, GEMM_SMEM>>>(
        p_x16, p_wq16, p_qkv16, HID, HID / 8, F3 / 8, F3);

    // 2. pass 1: Z[q] = sum_k 2^(q'.k)
    qk1_kernel<<<dim3(SEQ / 512, SEQ / 128, NBH), blk>>>(p_qkv16, p_z);

    // 3. pass 2 (transposed): colsum[k] = sum_q 2^(q'.k)/Z[q]
    qk2_kernel<<<dim3(SEQ / 128, QSTRIPS, NBH), blk, QK2_SMEM>>>(p_qkv16, p_z, p_cs);

    // 4. vals16 = fp16(v * colsum)
    scale_v16_kernel<<<(int)(((long)BS * HID / 8) / 256), blk>>>(p_qkv16, p_cs, p_vals16);

    // 5. out(fp32) = vals16 @ wo16
    gemm_f16<false><<<dim3(HID / 128, BS / 128), blk, GEMM_SMEM>>>(
        p_vals16, p_wo16, out, HID, HID / 8, HID / 8, HID);
}